// round 13
// baseline (speedup 1.0000x reference)
#include <cuda_runtime.h>
#include <cuda_fp16.h>
#include <cstdint>

#define N_NODES 40000
#define N_EDGES 640000
#define IN_F    128
#define HID     256
#define CLS     40
#define ROW4    (IN_F/4)
#define ROWH    32
#define GRID_B  625           // build-kernel grid (co-resident: 148 SMs x 5)
#define NPB     64            // nodes per build block (625*64 = 40000)

typedef unsigned long long ull;

// packed f32x2 helpers
#define FMA2(d, a, b)    asm("fma.rn.f32x2 %0, %1, %2, %3;" : "=l"(d) : "l"(a), "l"(b), "l"(d))
#define UNPACK2(lo, hi, s) asm("mov.b64 {%0, %1}, %2;" : "=f"(lo), "=f"(hi) : "l"(s))

__device__ __forceinline__ uint2 pack4h(float4 a) {
    __half2 lo = __floats2half2_rn(a.x, a.y);
    __half2 hi = __floats2half2_rn(a.z, a.w);
    uint2 r;
    r.x = *reinterpret_cast<unsigned*>(&lo);
    r.y = *reinterpret_cast<unsigned*>(&hi);
    return r;
}
__device__ __forceinline__ float4 unpack4h(uint2 v) {
    __half2 lo = *reinterpret_cast<__half2*>(&v.x);
    __half2 hi = *reinterpret_cast<__half2*>(&v.y);
    float2 a = __half22float2(lo);
    float2 b = __half22float2(hi);
    return make_float4(a.x, a.y, b.x, b.y);
}

// ---- scratch ----
__device__ int      g_deg[N_NODES];
__device__ int      g_rowptr[N_NODES + 1];
__device__ int      g_cursor[N_NODES];
__device__ int      g_part[GRID_B];
__device__ int      g_csr[N_EDGES];
__device__ float    g_norm[N_NODES];
__device__ uint2    g_featH[N_NODES * ROWH];  // feat*norm fp16; REUSED as hop2 out
__device__ uint2    g_bufH[N_NODES * ROWH];   // hop1 out, fp16
__device__ __half   g_W1h[HID * IN_F];        // W1^T fp16: [n][k]
__device__ unsigned g_bar_gen;                // global barrier (generation)
__device__ unsigned g_bar_cnt;

// ---- software global barrier (all GRID_B blocks co-resident by construction) ----
__device__ __forceinline__ void gbar() {
    __syncthreads();
    if (threadIdx.x == 0) {
        __threadfence();
        unsigned gen = atomicAdd(&g_bar_gen, 0u);          // read BEFORE arrive
        unsigned arr = atomicAdd(&g_bar_cnt, 1u);
        if (arr == GRID_B - 1) {
            atomicExch(&g_bar_cnt, 0u);                    // reset before release
            __threadfence();
            atomicAdd(&g_bar_gen, 1u);                     // release
        } else {
            while (atomicAdd(&g_bar_gen, 0u) == gen) { }   // spin
        }
        __threadfence();
    }
    __syncthreads();
}

// ================= persistent build kernel =================
// Phases: 0 zero-deg + W1 prep | 1 degree | 2 scan partials | 3 prefix +
// rowptr/cursor/norm + prescale | 4 CSR fill | 5 per-node sort.
__global__ __launch_bounds__(256, 5)
void k_build(const int4* __restrict__ src4, const int4* __restrict__ dst4,
             const float* __restrict__ W1, const float4* __restrict__ feat4) {
    __shared__ int   s_scan[NPB];
    __shared__ float s_norm[NPB];
    __shared__ int   s_red[256];
    __shared__ int   s_sort[8][512];

    const int t  = threadIdx.x;
    const int b  = blockIdx.x;
    const int gt = b * 256 + t;                  // 0 .. 159999

    // ---- phase 0: zero degree + W1^T fp16 prep ----
    if (gt < N_NODES) g_deg[gt] = 0;
    if (gt < HID * IN_F) {
        int k = gt >> 8, n = gt & 255;
        g_W1h[n * IN_F + k] = __float2half(W1[gt]);
    }
    gbar();

    // ---- phase 1: degree (4 edges/thread, 160000 threads exact) ----
    {
        int4 d = dst4[gt];
        atomicAdd(&g_deg[d.x], 1);
        atomicAdd(&g_deg[d.y], 1);
        atomicAdd(&g_deg[d.z], 1);
        atomicAdd(&g_deg[d.w], 1);
    }
    gbar();

    // ---- phase 2: block-local inclusive scan of 64 degrees ----
    {
        int v = (t < NPB) ? g_deg[b * NPB + t] : 0;
        if (t < NPB) s_scan[t] = v;
        __syncthreads();
        int acc = v;
        #pragma unroll
        for (int o = 1; o < NPB; o <<= 1) {
            int u = (t >= o && t < NPB) ? s_scan[t - o] : 0;
            __syncthreads();
            if (t < NPB) { acc += u; s_scan[t] = acc; }
            __syncthreads();
        }
        if (t == 0) g_part[b] = s_scan[NPB - 1];
    }
    gbar();

    // ---- phase 3: cross-block prefix + rowptr/cursor/norm + prescale ----
    {
        int loc = 0;
        for (int i = t; i < b; i += 256) loc += g_part[i];
        s_red[t] = loc;
        __syncthreads();
        #pragma unroll
        for (int o = 128; o > 0; o >>= 1) {
            if (t < o) s_red[t] += s_red[t + o];
            __syncthreads();
        }
        int off = s_red[0];

        if (t < NPB) {
            int node = b * NPB + t;
            int inc  = s_scan[t];
            int exc  = (t == 0) ? 0 : s_scan[t - 1];
            int rp   = off + exc;
            g_rowptr[node] = rp;
            g_cursor[node] = rp;
            float nrm = rsqrtf(fmaxf((float)(inc - exc), 1.0f));
            g_norm[node] = nrm;
            s_norm[t] = nrm;
        }
        if (b == GRID_B - 1 && t == 0) g_rowptr[N_NODES] = off + s_scan[NPB - 1];
        __syncthreads();

        // prescale: 64 nodes x 32 float4 = 2048 float4, 8 per thread, coalesced
        const int nodeBase = b * NPB;
        #pragma unroll
        for (int it = 0; it < 8; it++) {
            int idx  = it * 256 + t;                 // 0..2047
            int node = nodeBase + (idx >> 5);
            float n  = s_norm[idx >> 5];
            float4 x = feat4[node * ROWH + (idx & 31)];
            x.x *= n; x.y *= n; x.z *= n; x.w *= n;
            g_featH[node * ROWH + (idx & 31)] = pack4h(x);
        }
    }
    gbar();

    // ---- phase 4: CSR fill ----
    {
        int4 s = src4[gt];
        int4 d = dst4[gt];
        g_csr[atomicAdd(&g_cursor[d.x], 1)] = s.x;
        g_csr[atomicAdd(&g_cursor[d.y], 1)] = s.y;
        g_csr[atomicAdd(&g_cursor[d.z], 1)] = s.z;
        g_csr[atomicAdd(&g_cursor[d.w], 1)] = s.w;
    }
    gbar();

    // ---- phase 5: per-node sort (warp/node; 5000 warps x 8 nodes) ----
    {
        const int wi   = t >> 5;
        const int lane = t & 31;
        const int gw   = b * 8 + wi;                 // 0..4999
        for (int n = gw; n < N_NODES; n += GRID_B * 8) {
            int beg = g_rowptr[n], end = g_rowptr[n + 1];
            int d = end - beg;
            if (d <= 1) continue;
            if (d <= 32) {
                int v = (lane < d) ? g_csr[beg + lane] : 0x7fffffff;
                #pragma unroll
                for (int k = 2; k <= 32; k <<= 1) {
                    #pragma unroll
                    for (int j = k >> 1; j > 0; j >>= 1) {
                        int pv = __shfl_xor_sync(0xffffffffu, v, j);
                        bool dir   = ((lane & k) == 0);
                        bool lower = ((lane & j) == 0);
                        v = ((lower == dir) ? min(v, pv) : max(v, pv));
                    }
                }
                if (lane < d) g_csr[beg + lane] = v;
            } else if (d <= 512) {
                int* s = s_sort[wi];
                int n2 = 64; while (n2 < d) n2 <<= 1;
                for (int i = lane; i < n2; i += 32)
                    s[i] = (i < d) ? g_csr[beg + i] : 0x7fffffff;
                __syncwarp();
                for (int k = 2; k <= n2; k <<= 1) {
                    for (int j = k >> 1; j > 0; j >>= 1) {
                        for (int i = lane; i < n2; i += 32) {
                            int p = i ^ j;
                            if (p > i) {
                                int a = s[i], c = s[p];
                                bool dir = ((i & k) == 0);
                                if ((a > c) == dir) { s[i] = c; s[p] = a; }
                            }
                        }
                        __syncwarp();
                    }
                }
                for (int i = lane; i < d; i += 32) g_csr[beg + i] = s[i];
            } else if (lane == 0) {                  // unreachable safety net
                for (int i = beg + 1; i < end; i++) {
                    int v = g_csr[i], j = i - 1;
                    while (j >= beg && g_csr[j] > v) { g_csr[j + 1] = g_csr[j]; j--; }
                    g_csr[j + 1] = v;
                }
            }
        }
    }
}

// ================= hop 1 gather =================
__global__ __launch_bounds__(256)
void k_gather1() {
    int gt = blockIdx.x * blockDim.x + threadIdx.x;
    int w = gt >> 5, lane = gt & 31;
    int beg = g_rowptr[w], end = g_rowptr[w + 1];
    float4 acc = make_float4(0.f, 0.f, 0.f, 0.f);
    for (int base = beg; base < end; base += 32) {
        int cnt = min(32, end - base);
        int idx = base + lane;
        int s_l = (idx < end) ? g_csr[idx] : 0;
        int k = 0;
        for (; k + 8 <= cnt; k += 8) {
            int s[8];
            #pragma unroll
            for (int i = 0; i < 8; i++) s[i] = __shfl_sync(0xffffffffu, s_l, k + i);
            uint2 h[8];
            #pragma unroll
            for (int i = 0; i < 8; i++) h[i] = g_featH[s[i] * ROWH + lane];
            #pragma unroll
            for (int i = 0; i < 8; i++) {
                float4 v = unpack4h(h[i]);
                acc.x += v.x; acc.y += v.y; acc.z += v.z; acc.w += v.w;
            }
        }
        for (; k < cnt; k++) {
            int s = __shfl_sync(0xffffffffu, s_l, k);
            float4 v = unpack4h(g_featH[s * ROWH + lane]);
            acc.x += v.x; acc.y += v.y; acc.z += v.z; acc.w += v.w;
        }
    }
    float nn = g_norm[w];
    float sc = nn * nn;
    acc.x *= sc; acc.y *= sc; acc.z *= sc; acc.w *= sc;
    g_bufH[w * ROWH + lane] = pack4h(acc);
}

// ================= hop 2 gather (writes into dead g_featH) =================
__global__ __launch_bounds__(256)
void k_gather2() {
    int gt = blockIdx.x * blockDim.x + threadIdx.x;
    int w = gt >> 5, lane = gt & 31;
    int beg = g_rowptr[w], end = g_rowptr[w + 1];
    float4 acc = make_float4(0.f, 0.f, 0.f, 0.f);
    for (int base = beg; base < end; base += 32) {
        int cnt = min(32, end - base);
        int idx = base + lane;
        int s_l = (idx < end) ? g_csr[idx] : 0;
        int k = 0;
        for (; k + 8 <= cnt; k += 8) {
            int s[8];
            #pragma unroll
            for (int i = 0; i < 8; i++) s[i] = __shfl_sync(0xffffffffu, s_l, k + i);
            uint2 h[8];
            #pragma unroll
            for (int i = 0; i < 8; i++) h[i] = g_bufH[s[i] * ROWH + lane];
            #pragma unroll
            for (int i = 0; i < 8; i++) {
                float4 v = unpack4h(h[i]);
                acc.x += v.x; acc.y += v.y; acc.z += v.z; acc.w += v.w;
            }
        }
        for (; k < cnt; k++) {
            int s = __shfl_sync(0xffffffffu, s_l, k);
            float4 v = unpack4h(g_bufH[s * ROWH + lane]);
            acc.x += v.x; acc.y += v.y; acc.z += v.z; acc.w += v.w;
        }
    }
    float nn = g_norm[w];
    acc.x *= nn; acc.y *= nn; acc.z *= nn; acc.w *= nn;
    g_featH[w * ROWH + lane] = pack4h(acc);
}

// ================= MLP via mma.sync (HMMA) =================
#define HPAD 68
#define ZSTR 264
#define MLP_SMEM 129024
__global__ __launch_bounds__(256)
void k_mlp(const float* __restrict__ b1, const float* __restrict__ W2,
           const float* __restrict__ b2, float* __restrict__ out) {
    extern __shared__ __align__(16) char dyn[];
    unsigned* smHA  = reinterpret_cast<unsigned*>(dyn);                // fp16 [64][136]
    unsigned* smW1  = reinterpret_cast<unsigned*>(dyn + 17408);        // fp16 [256][136]
    float*    smZ   = reinterpret_cast<float*>(dyn + 17408);           // fp32 [64][264]
    float*    smW2  = reinterpret_cast<float*>(dyn + 87040);           // fp32 [40][256]
    float*    smB1  = reinterpret_cast<float*>(dyn + 128000);          // fp32 [256]

    const int t    = threadIdx.x;
    const int wid  = t >> 5;
    const int lane = t & 31;
    const int row0 = blockIdx.x * 64;

    const unsigned* srcH = reinterpret_cast<const unsigned*>(g_featH) + row0 * 64;
    #pragma unroll
    for (int it = 0; it < 16; it++) {
        int idx = it * 256 + t;
        int r = idx >> 6, c = idx & 63;
        smHA[r * HPAD + c] = srcH[idx];
    }
    {
        const uint4* srcW = reinterpret_cast<const uint4*>(g_W1h);
        uint4* dstW = reinterpret_cast<uint4*>(smW1);
        #pragma unroll
        for (int it = 0; it < 16; it++) {
            int idx = it * 256 + t;
            int r = idx >> 4, q = idx & 15;
            dstW[r * 17 + q] = srcW[idx];
        }
    }
    smB1[t] = b1[t];
    __syncthreads();

    const int mrow0 = (wid & 3) * 16;
    const int ncol0 = (wid >> 2) * 128;
    const int g  = lane >> 2;
    const int ct = lane & 3;

    float acc[16][4];
    #pragma unroll
    for (int nt = 0; nt < 16; nt++)
        #pragma unroll
        for (int q = 0; q < 4; q++) acc[nt][q] = 0.f;

    #pragma unroll
    for (int kt = 0; kt < 8; kt++) {
        const int kw = kt * 8 + ct;
        unsigned a0 = smHA[(mrow0 + g) * HPAD + kw];
        unsigned a1 = smHA[(mrow0 + g + 8) * HPAD + kw];
        unsigned a2 = smHA[(mrow0 + g) * HPAD + kw + 4];
        unsigned a3 = smHA[(mrow0 + g + 8) * HPAD + kw + 4];
        #pragma unroll
        for (int nt = 0; nt < 16; nt++) {
            const int n = ncol0 + nt * 8 + g;
            unsigned b0 = smW1[n * HPAD + kw];
            unsigned b1r = smW1[n * HPAD + kw + 4];
            asm volatile(
                "mma.sync.aligned.m16n8k16.row.col.f32.f16.f16.f32 "
                "{%0,%1,%2,%3}, {%4,%5,%6,%7}, {%8,%9}, {%0,%1,%2,%3};"
                : "+f"(acc[nt][0]), "+f"(acc[nt][1]), "+f"(acc[nt][2]), "+f"(acc[nt][3])
                : "r"(a0), "r"(a1), "r"(a2), "r"(a3), "r"(b0), "r"(b1r));
        }
    }

    for (int i = t; i < CLS * HID; i += 256) {
        int c = i >> 8, k = i & 255;
        smW2[c * HID + k] = W2[k * CLS + c];
    }

    __syncthreads();
    #pragma unroll
    for (int nt = 0; nt < 16; nt++) {
        const int col = ncol0 + nt * 8 + ct * 2;
        float bi0 = smB1[col], bi1 = smB1[col + 1];
        float2 z0, z1;
        z0.x = fmaxf(acc[nt][0] + bi0, 0.f);
        z0.y = fmaxf(acc[nt][1] + bi1, 0.f);
        z1.x = fmaxf(acc[nt][2] + bi0, 0.f);
        z1.y = fmaxf(acc[nt][3] + bi1, 0.f);
        *reinterpret_cast<float2*>(smZ + (mrow0 + g) * ZSTR + col)     = z0;
        *reinterpret_cast<float2*>(smZ + (mrow0 + g + 8) * ZSTR + col) = z1;
    }
    __syncthreads();

    const int rbase = wid * 8;
    ull zp[8][4];
    #pragma unroll
    for (int rr = 0; rr < 8; rr++) {
        const ulonglong2* zr =
            reinterpret_cast<const ulonglong2*>(smZ + (rbase + rr) * ZSTR + lane * 8);
        ulonglong2 a = zr[0], b = zr[1];
        zp[rr][0] = a.x; zp[rr][1] = a.y; zp[rr][2] = b.x; zp[rr][3] = b.y;
    }
    #pragma unroll 1
    for (int c = 0; c < CLS; c++) {
        const ulonglong2* wp =
            reinterpret_cast<const ulonglong2*>(smW2 + c * HID + lane * 8);
        ulonglong2 wA = wp[0], wB = wp[1];
        float p[8];
        #pragma unroll
        for (int rr = 0; rr < 8; rr++) {
            ull s2 = 0ull;
            FMA2(s2, zp[rr][0], wA.x);
            FMA2(s2, zp[rr][1], wA.y);
            FMA2(s2, zp[rr][2], wB.x);
            FMA2(s2, zp[rr][3], wB.y);
            float lo, hi;
            UNPACK2(lo, hi, s2);
            p[rr] = lo + hi;
        }
        #pragma unroll
        for (int off = 16; off > 0; off >>= 1) {
            #pragma unroll
            for (int rr = 0; rr < 8; rr++)
                p[rr] += __shfl_xor_sync(0xffffffffu, p[rr], off);
        }
        if (lane == 0) {
            float bc = b2[c];
            #pragma unroll
            for (int rr = 0; rr < 8; rr++)
                out[(row0 + rbase + rr) * CLS + c] = p[rr] + bc;
        }
    }
}

// ================= launch =================
extern "C" void kernel_launch(void* const* d_in, const int* in_sizes, int n_in,
                              void* d_out, int out_size) {
    const float* features = (const float*)d_in[0];
    const int*   src      = (const int*)d_in[1];
    const int*   dst      = (const int*)d_in[2];
    const float* W1       = (const float*)d_in[3];
    const float* b1       = (const float*)d_in[4];
    const float* W2       = (const float*)d_in[5];
    const float* b2       = (const float*)d_in[6];
    float* out = (float*)d_out;

    const int warpBlocks = N_NODES * 32 / 256;      // 5000
    const int mlpBlocks  = N_NODES / 64;            // 625

    static int init_done = 0;
    if (!init_done) {
        cudaFuncSetAttribute(k_mlp, cudaFuncAttributeMaxDynamicSharedMemorySize,
                             MLP_SMEM);
        init_done = 1;
    }

    k_build<<<GRID_B, 256>>>((const int4*)src, (const int4*)dst, W1,
                             (const float4*)features);
    k_gather1<<<warpBlocks, 256>>>();
    k_gather2<<<warpBlocks, 256>>>();
    k_mlp<<<mlpBlocks, 256, MLP_SMEM>>>(b1, W2, b2, out);
}

// round 14
// speedup vs baseline: 1.8410x; 1.8410x over previous
#include <cuda_runtime.h>
#include <cuda_fp16.h>
#include <cstdint>

#define N_NODES 40000
#define N_EDGES 640000
#define IN_F    128
#define HID     256
#define CLS     40
#define ROW4    (IN_F/4)
#define ROWH    32
#define NBLK    157
#define W2KP    264           // padded K for W2^T fp16 (256 + 8)

typedef unsigned long long ull;

__device__ __forceinline__ uint2 pack4h(float4 a) {
    __half2 lo = __floats2half2_rn(a.x, a.y);
    __half2 hi = __floats2half2_rn(a.z, a.w);
    uint2 r;
    r.x = *reinterpret_cast<unsigned*>(&lo);
    r.y = *reinterpret_cast<unsigned*>(&hi);
    return r;
}
__device__ __forceinline__ float4 unpack4h(uint2 v) {
    __half2 lo = *reinterpret_cast<__half2*>(&v.x);
    __half2 hi = *reinterpret_cast<__half2*>(&v.y);
    float2 a = __half22float2(lo);
    float2 b = __half22float2(hi);
    return make_float4(a.x, a.y, b.x, b.y);
}
__device__ __forceinline__ unsigned packh2(float lo, float hi) {
    __half2 h = __floats2half2_rn(lo, hi);
    return *reinterpret_cast<unsigned*>(&h);
}

// ---- scratch ----
__device__ int    g_deg[N_NODES];
__device__ int    g_rowptr[N_NODES + 1];
__device__ int    g_cursor[N_NODES];
__device__ int    g_part[NBLK];             // lookback partials (init -1 by k_deg4)
__device__ int    g_csr[N_EDGES];
__device__ float  g_norm[N_NODES];
__device__ uint2  g_featH[N_NODES * ROWH];  // feat*norm fp16; REUSED as hop2 out
__device__ uint2  g_bufH[N_NODES * ROWH];   // hop1 out, fp16
__device__ __half g_W1h[HID * IN_F];        // W1^T fp16: [n][k]
__device__ __align__(16) __half g_W2h[CLS * W2KP];  // W2^T fp16: [c][k], k-padded

// ================= degree + weight prep + sentinels =================
__global__ __launch_bounds__(256)
void k_deg4(const int4* __restrict__ dst4, const float* __restrict__ W1,
            const float* __restrict__ W2) {
    int e = blockIdx.x * blockDim.x + threadIdx.x;   // 625 blocks -> 640000 edges
    int4 d = dst4[e];
    atomicAdd(&g_deg[d.x], 1);
    atomicAdd(&g_deg[d.y], 1);
    atomicAdd(&g_deg[d.z], 1);
    atomicAdd(&g_deg[d.w], 1);
    if (blockIdx.x < 128) {                          // W1^T fp16 (32768 elems)
        int i = blockIdx.x * 256 + threadIdx.x;
        int k = i >> 8, n = i & 255;
        g_W1h[n * IN_F + k] = __float2half(W1[i]);
    } else if (blockIdx.x < 168) {                   // W2^T fp16 (10240 elems)
        int i = (blockIdx.x - 128) * 256 + threadIdx.x;
        int k = i / CLS, c = i - k * CLS;
        g_W2h[c * W2KP + k] = __float2half(W2[i]);
    } else if (blockIdx.x == 168 && threadIdx.x < CLS * 8) {   // zero k-pad
        int c = threadIdx.x >> 3, k = 256 + (threadIdx.x & 7);
        g_W2h[c * W2KP + k] = __float2half(0.f);
    }
    if (blockIdx.x == 624 && threadIdx.x < NBLK)
        g_part[threadIdx.x] = -1;
}

// ================= scan (lookback) + cursor + norm + prescale =================
__global__ __launch_bounds__(256)
void k_scan(const float4* __restrict__ feat4) {
    __shared__ int   sm[256];
    __shared__ float smN[256];
    const int t = threadIdx.x;
    const int b = blockIdx.x;
    const int i = b * 256 + t;
    int v = (i < N_NODES) ? g_deg[i] : 0;

    sm[t] = v;
    __syncthreads();
    int acc = v;
    for (int o = 1; o < 256; o <<= 1) {
        int u = (t >= o) ? sm[t - o] : 0;
        __syncthreads();
        acc += u;
        sm[t] = acc;
        __syncthreads();
    }
    int S = sm[255];

    if (t == 0) atomicExch(&g_part[b], S);

    int part = 0;
    if (t < b) {
        int p;
        do { p = atomicAdd(&g_part[t], 0); } while (p < 0);
        part = p;
    }
    __syncthreads();
    sm[t] = part;
    __syncthreads();
    for (int o = 128; o > 0; o >>= 1) {
        if (t < o) sm[t] += sm[t + o];
        __syncthreads();
    }
    int off = sm[0];

    float nrm = rsqrtf(fmaxf((float)v, 1.0f));
    smN[t] = nrm;
    if (i < N_NODES) {
        int rp = acc - v + off;
        g_rowptr[i] = rp;
        g_cursor[i] = rp;
        g_norm[i] = nrm;
    }
    if (b == NBLK - 1 && t == 0) g_rowptr[N_NODES] = off + S;
    __syncthreads();

    const int nodeBase = b * 256;
    for (int idx = t; idx < 256 * ROWH; idx += 256) {
        int node = nodeBase + (idx >> 5);
        if (node < N_NODES) {
            float n = smN[idx >> 5];
            float4 x = feat4[node * ROWH + (idx & 31)];
            x.x *= n; x.y *= n; x.z *= n; x.w *= n;
            g_featH[node * ROWH + (idx & 31)] = pack4h(x);
        }
    }
}

// ================= CSR fill =================
__global__ __launch_bounds__(256)
void k_fill4(const int4* __restrict__ src4, const int4* __restrict__ dst4) {
    int e = blockIdx.x * blockDim.x + threadIdx.x;
    int4 s = src4[e];
    int4 d = dst4[e];
    g_csr[atomicAdd(&g_cursor[d.x], 1)] = s.x;
    g_csr[atomicAdd(&g_cursor[d.y], 1)] = s.y;
    g_csr[atomicAdd(&g_cursor[d.z], 1)] = s.z;
    g_csr[atomicAdd(&g_cursor[d.w], 1)] = s.w;
}

// ================= per-node sort =================
__global__ __launch_bounds__(256)
void k_sort() {
    __shared__ int scratch[8][512];
    const int wi   = threadIdx.x >> 5;
    const int lane = threadIdx.x & 31;
    const int n = blockIdx.x * 8 + wi;
    int b = g_rowptr[n], e = g_rowptr[n + 1];
    int d = e - b;
    if (d <= 1) return;
    if (d <= 32) {
        int v = (lane < d) ? g_csr[b + lane] : 0x7fffffff;
        #pragma unroll
        for (int k = 2; k <= 32; k <<= 1) {
            #pragma unroll
            for (int j = k >> 1; j > 0; j >>= 1) {
                int pv = __shfl_xor_sync(0xffffffffu, v, j);
                bool dir   = ((lane & k) == 0);
                bool lower = ((lane & j) == 0);
                v = ((lower == dir) ? min(v, pv) : max(v, pv));
            }
        }
        if (lane < d) g_csr[b + lane] = v;
    } else if (d <= 512) {
        int* s = scratch[wi];
        int n2 = 64; while (n2 < d) n2 <<= 1;
        for (int i = lane; i < n2; i += 32) s[i] = (i < d) ? g_csr[b + i] : 0x7fffffff;
        __syncwarp();
        for (int k = 2; k <= n2; k <<= 1) {
            for (int j = k >> 1; j > 0; j >>= 1) {
                for (int i = lane; i < n2; i += 32) {
                    int p = i ^ j;
                    if (p > i) {
                        int a = s[i], c = s[p];
                        bool dir = ((i & k) == 0);
                        if ((a > c) == dir) { s[i] = c; s[p] = a; }
                    }
                }
                __syncwarp();
            }
        }
        for (int i = lane; i < d; i += 32) g_csr[b + i] = s[i];
    } else {
        if (lane == 0) {
            for (int i = b + 1; i < e; i++) {
                int v = g_csr[i], j = i - 1;
                while (j >= b && g_csr[j] > v) { g_csr[j + 1] = g_csr[j]; j--; }
                g_csr[j + 1] = v;
            }
        }
    }
}

// ================= gathers =================
__global__ __launch_bounds__(256)
void k_gather1() {
    int gt = blockIdx.x * blockDim.x + threadIdx.x;
    int w = gt >> 5, lane = gt & 31;
    int beg = g_rowptr[w], end = g_rowptr[w + 1];
    float4 acc = make_float4(0.f, 0.f, 0.f, 0.f);
    for (int base = beg; base < end; base += 32) {
        int cnt = min(32, end - base);
        int idx = base + lane;
        int s_l = (idx < end) ? g_csr[idx] : 0;
        int k = 0;
        for (; k + 8 <= cnt; k += 8) {
            int s[8];
            #pragma unroll
            for (int i = 0; i < 8; i++) s[i] = __shfl_sync(0xffffffffu, s_l, k + i);
            uint2 h[8];
            #pragma unroll
            for (int i = 0; i < 8; i++) h[i] = g_featH[s[i] * ROWH + lane];
            #pragma unroll
            for (int i = 0; i < 8; i++) {
                float4 v = unpack4h(h[i]);
                acc.x += v.x; acc.y += v.y; acc.z += v.z; acc.w += v.w;
            }
        }
        for (; k < cnt; k++) {
            int s = __shfl_sync(0xffffffffu, s_l, k);
            float4 v = unpack4h(g_featH[s * ROWH + lane]);
            acc.x += v.x; acc.y += v.y; acc.z += v.z; acc.w += v.w;
        }
    }
    float nn = g_norm[w];
    float sc = nn * nn;
    acc.x *= sc; acc.y *= sc; acc.z *= sc; acc.w *= sc;
    g_bufH[w * ROWH + lane] = pack4h(acc);
}

__global__ __launch_bounds__(256)
void k_gather2() {
    int gt = blockIdx.x * blockDim.x + threadIdx.x;
    int w = gt >> 5, lane = gt & 31;
    int beg = g_rowptr[w], end = g_rowptr[w + 1];
    float4 acc = make_float4(0.f, 0.f, 0.f, 0.f);
    for (int base = beg; base < end; base += 32) {
        int cnt = min(32, end - base);
        int idx = base + lane;
        int s_l = (idx < end) ? g_csr[idx] : 0;
        int k = 0;
        for (; k + 8 <= cnt; k += 8) {
            int s[8];
            #pragma unroll
            for (int i = 0; i < 8; i++) s[i] = __shfl_sync(0xffffffffu, s_l, k + i);
            uint2 h[8];
            #pragma unroll
            for (int i = 0; i < 8; i++) h[i] = g_bufH[s[i] * ROWH + lane];
            #pragma unroll
            for (int i = 0; i < 8; i++) {
                float4 v = unpack4h(h[i]);
                acc.x += v.x; acc.y += v.y; acc.z += v.z; acc.w += v.w;
            }
        }
        for (; k < cnt; k++) {
            int s = __shfl_sync(0xffffffffu, s_l, k);
            float4 v = unpack4h(g_bufH[s * ROWH + lane]);
            acc.x += v.x; acc.y += v.y; acc.z += v.z; acc.w += v.w;
        }
    }
    float nn = g_norm[w];
    acc.x *= nn; acc.y *= nn; acc.z *= nn; acc.w *= nn;
    g_featH[w * ROWH + lane] = pack4h(acc);
}

// ================= MLP: both GEMMs via mma.sync (HMMA) =================
// CTA = 64 rows, 256 threads (8 warps). Warp w: m-tile (w&3), K-half (w>>2).
// GEMM1: z[64][256] = h @ W1 (16 n8-tiles per warp).
// GEMM2: out[64][40] = relu(z+b1) @ W2; z fragments repacked fp16 in registers
// (GEMM1 C-fragment layout == GEMM2 A-fragment layout), W2^T fp16 from smem,
// cross-K-half partials combined through smem.
// smem: smHA [64][136]h @0 (17408) | smW1 [256][136]h @17408 (69632)
//       union: smW2T [40][264]h @17408 (21120), smC fp32 2x2560 @38528 (20480)
//       smB1 [256]f @87040 (1024) -> total 88064 B => 2 CTAs/SM
#define HPAD 68
#define MLP_SMEM 88064
__global__ __launch_bounds__(256)
void k_mlp(const float* __restrict__ b1, const float* __restrict__ b2,
           float* __restrict__ out) {
    extern __shared__ __align__(16) char dyn[];
    unsigned* smHA  = reinterpret_cast<unsigned*>(dyn);
    unsigned* smW1  = reinterpret_cast<unsigned*>(dyn + 17408);
    unsigned* smW2  = reinterpret_cast<unsigned*>(dyn + 17408);   // union (words)
    float*    smC   = reinterpret_cast<float*>(dyn + 38528);      // [2][2560]
    float*    smB1  = reinterpret_cast<float*>(dyn + 87040);

    const int t    = threadIdx.x;
    const int wid  = t >> 5;
    const int lane = t & 31;
    const int row0 = blockIdx.x * 64;

    // ---- load h tile (fp16) ----
    const unsigned* srcH = reinterpret_cast<const unsigned*>(g_featH) + row0 * 64;
    #pragma unroll
    for (int it = 0; it < 16; it++) {
        int idx = it * 256 + t;
        int r = idx >> 6, c = idx & 63;
        smHA[r * HPAD + c] = srcH[idx];
    }
    // ---- load W1T (fp16) ----
    {
        const uint4* srcW = reinterpret_cast<const uint4*>(g_W1h);
        uint4* dstW = reinterpret_cast<uint4*>(smW1);
        #pragma unroll
        for (int it = 0; it < 16; it++) {
            int idx = it * 256 + t;
            int r = idx >> 4, q = idx & 15;
            dstW[r * 17 + q] = srcW[idx];
        }
    }
    smB1[t] = b1[t];
    __syncthreads();

    const int mrow0 = (wid & 3) * 16;
    const int ncol0 = (wid >> 2) * 128;
    const int g  = lane >> 2;
    const int ct = lane & 3;

    // ---- GEMM1 ----
    float acc[16][4];
    #pragma unroll
    for (int nt = 0; nt < 16; nt++)
        #pragma unroll
        for (int q = 0; q < 4; q++) acc[nt][q] = 0.f;

    #pragma unroll
    for (int kt = 0; kt < 8; kt++) {
        const int kw = kt * 8 + ct;
        unsigned a0 = smHA[(mrow0 + g) * HPAD + kw];
        unsigned a1 = smHA[(mrow0 + g + 8) * HPAD + kw];
        unsigned a2 = smHA[(mrow0 + g) * HPAD + kw + 4];
        unsigned a3 = smHA[(mrow0 + g + 8) * HPAD + kw + 4];
        #pragma unroll
        for (int nt = 0; nt < 16; nt++) {
            const int n = ncol0 + nt * 8 + g;
            unsigned b0 = smW1[n * HPAD + kw];
            unsigned b1r = smW1[n * HPAD + kw + 4];
            asm volatile(
                "mma.sync.aligned.m16n8k16.row.col.f32.f16.f16.f32 "
                "{%0,%1,%2,%3}, {%4,%5,%6,%7}, {%8,%9}, {%0,%1,%2,%3};"
                : "+f"(acc[nt][0]), "+f"(acc[nt][1]), "+f"(acc[nt][2]), "+f"(acc[nt][3])
                : "r"(a0), "r"(a1), "r"(a2), "r"(a3), "r"(b0), "r"(b1r));
        }
    }

    // ---- bias + relu + pack z fragments (registers only) ----
    // k-step s uses acc tiles 2s, 2s+1: A-frag {(g,k01),(g+8,k01),(g,k89),(g+8,k89)}
    unsigned zf[8][4];
    #pragma unroll
    for (int s = 0; s < 8; s++) {
        int c0 = ncol0 + (2 * s) * 8 + ct * 2;
        int c1 = ncol0 + (2 * s + 1) * 8 + ct * 2;
        float bi0 = smB1[c0], bi1 = smB1[c0 + 1];
        float bi2 = smB1[c1], bi3 = smB1[c1 + 1];
        zf[s][0] = packh2(fmaxf(acc[2*s][0] + bi0, 0.f),   fmaxf(acc[2*s][1] + bi1, 0.f));
        zf[s][1] = packh2(fmaxf(acc[2*s][2] + bi0, 0.f),   fmaxf(acc[2*s][3] + bi1, 0.f));
        zf[s][2] = packh2(fmaxf(acc[2*s+1][0] + bi2, 0.f), fmaxf(acc[2*s+1][1] + bi3, 0.f));
        zf[s][3] = packh2(fmaxf(acc[2*s+1][2] + bi2, 0.f), fmaxf(acc[2*s+1][3] + bi3, 0.f));
    }
    __syncthreads();   // all warps done reading smW1

    // ---- load W2^T fp16 into union region: 1320 uint4 ----
    {
        const uint4* srcW = reinterpret_cast<const uint4*>(g_W2h);
        uint4* dstW = reinterpret_cast<uint4*>(smW2);
        for (int i = t; i < (CLS * W2KP) / 8; i += 256) dstW[i] = srcW[i];
    }
    __syncthreads();

    // ---- GEMM2: 5 c-tiles x 8 k-steps of m16n8k16 ----
    float C[5][4];
    #pragma unroll
    for (int c = 0; c < 5; c++)
        #pragma unroll
        for (int q = 0; q < 4; q++) C[c][q] = 0.f;

    const int wbase = (ncol0 >> 1);          // word offset of this warp's K half
    #pragma unroll
    for (int s = 0; s < 8; s++) {
        #pragma unroll
        for (int c = 0; c < 5; c++) {
            int word = (c * 8 + g) * (W2KP / 2) + wbase + s * 8 + ct;
            unsigned b0 = smW2[word];
            unsigned b1r = smW2[word + 4];
            asm volatile(
                "mma.sync.aligned.m16n8k16.row.col.f32.f16.f16.f32 "
                "{%0,%1,%2,%3}, {%4,%5,%6,%7}, {%8,%9}, {%0,%1,%2,%3};"
                : "+f"(C[c][0]), "+f"(C[c][1]), "+f"(C[c][2]), "+f"(C[c][3])
                : "r"(zf[s][0]), "r"(zf[s][1]), "r"(zf[s][2]), "r"(zf[s][3]),
                  "r"(b0), "r"(b1r));
        }
    }

    // ---- write K-half partials ----
    {
        float* myC = smC + (wid >> 2) * 2560;
        #pragma unroll
        for (int c = 0; c < 5; c++) {
            int col = c * 8 + ct * 2;
            *reinterpret_cast<float2*>(myC + (mrow0 + g) * CLS + col) =
                make_float2(C[c][0], C[c][1]);
            *reinterpret_cast<float2*>(myC + (mrow0 + g + 8) * CLS + col) =
                make_float2(C[c][2], C[c][3]);
        }
    }
    __syncthreads();

    // ---- combine halves + bias, write out ----
    for (int i = t; i < 64 * CLS; i += 256) {
        int c = i % CLS;
        out[row0 * CLS + i] = smC[i] + smC[2560 + i] + b2[c];
    }
}

// ================= launch =================
extern "C" void kernel_launch(void* const* d_in, const int* in_sizes, int n_in,
                              void* d_out, int out_size) {
    const float* features = (const float*)d_in[0];
    const int*   src      = (const int*)d_in[1];
    const int*   dst      = (const int*)d_in[2];
    const float* W1       = (const float*)d_in[3];
    const float* b1       = (const float*)d_in[4];
    const float* W2       = (const float*)d_in[5];
    const float* b2       = (const float*)d_in[6];
    float* out = (float*)d_out;

    const int edge4Blocks = N_EDGES / 4 / 256;      // 625
    const int warpBlocks  = N_NODES * 32 / 256;     // 5000
    const int sortBlocks  = N_NODES / 8;            // 5000
    const int mlpBlocks   = N_NODES / 64;           // 625

    static int init_done = 0;
    if (!init_done) {
        cudaFuncSetAttribute(k_mlp, cudaFuncAttributeMaxDynamicSharedMemorySize,
                             MLP_SMEM);
        init_done = 1;
    }

    void* degPtr = nullptr;
    cudaGetSymbolAddress(&degPtr, g_deg);
    cudaMemsetAsync(degPtr, 0, N_NODES * sizeof(int));

    k_deg4<<<edge4Blocks, 256>>>((const int4*)dst, W1, W2);
    k_scan<<<NBLK, 256>>>((const float4*)features);
    k_fill4<<<edge4Blocks, 256>>>((const int4*)src, (const int4*)dst);
    k_sort<<<sortBlocks, 256>>>();
    k_gather1<<<warpBlocks, 256>>>();
    k_gather2<<<warpBlocks, 256>>>();
    k_mlp<<<mlpBlocks, 256, MLP_SMEM>>>(b1, b2, out);
}